// round 10
// baseline (speedup 1.0000x reference)
#include <cuda_runtime.h>
#include <cuda_fp16.h>
#include <math.h>

#define BB 16
#define HH 512
#define WW 512
#define NTOT (BB * HH * WW)

#define RAD 10
#define TILE_H 32
#define TILE_W 64
#define SROWS (TILE_H + 2 * RAD)  // 52
#define GX (WW / TILE_W)          // 8
#define GYT (HH / TILE_H)         // 16
#define NB (GX * GYT * BB)        // 2048

// Scratch (no allocation allowed in kernel_launch)
__device__ __half g_f2h[NTOT];   // horizontal distance^2 (<=100), fp16, 8.4MB
__device__ float g_pl[NB];
__device__ float g_pf[NB];
__device__ unsigned g_done = 0;  // last-block counter (self-resetting)

// ---------------------------------------------------------------------------
// K1: one WARP per image row. Each lane: 16 cols -> 16-bit fg mask; neighbor
// bits via 2 shfls; per-col horizontal distance f (clamped to 10: any d>=10
// gives heatmap <= exp(-100/8)=3.7e-6 ~ 0, loss-equivalent) via clz/ffs on a
// 21-bit window. Stores f^2 as fp16 (exact: integer <= 100).
// ---------------------------------------------------------------------------
__global__ __launch_bounds__(256) void k1_f2(const float* __restrict__ tgt) {
    const int gid = blockIdx.x * 256 + threadIdx.x;
    const int row = gid >> 5;
    const int lane = gid & 31;
    const float4* p = (const float4*)(tgt + (size_t)row * WW + lane * 16);
    float4 v0 = p[0], v1 = p[1], v2 = p[2], v3 = p[3];

    unsigned m = 0;
    m |= (v0.x > 0.5f) ? 1u << 0 : 0u;
    m |= (v0.y > 0.5f) ? 1u << 1 : 0u;
    m |= (v0.z > 0.5f) ? 1u << 2 : 0u;
    m |= (v0.w > 0.5f) ? 1u << 3 : 0u;
    m |= (v1.x > 0.5f) ? 1u << 4 : 0u;
    m |= (v1.y > 0.5f) ? 1u << 5 : 0u;
    m |= (v1.z > 0.5f) ? 1u << 6 : 0u;
    m |= (v1.w > 0.5f) ? 1u << 7 : 0u;
    m |= (v2.x > 0.5f) ? 1u << 8 : 0u;
    m |= (v2.y > 0.5f) ? 1u << 9 : 0u;
    m |= (v2.z > 0.5f) ? 1u << 10 : 0u;
    m |= (v2.w > 0.5f) ? 1u << 11 : 0u;
    m |= (v3.x > 0.5f) ? 1u << 12 : 0u;
    m |= (v3.y > 0.5f) ? 1u << 13 : 0u;
    m |= (v3.z > 0.5f) ? 1u << 14 : 0u;
    m |= (v3.w > 0.5f) ? 1u << 15 : 0u;

    unsigned left = __shfl_up_sync(0xffffffffu, m, 1);
    unsigned right = __shfl_down_sync(0xffffffffu, m, 1);
    if (lane == 0) left = 0;
    if (lane == 31) right = 0;
    unsigned long long w = (unsigned long long)left |
                           ((unsigned long long)m << 16) |
                           ((unsigned long long)right << 32);

    __half2 hout[8];
#pragma unroll
    for (int j = 0; j < 8; j++) {
        int f2p[2];
#pragma unroll
        for (int u = 0; u < 2; u++) {
            int pcol = 2 * j + u;
            unsigned win = (unsigned)(w >> (pcol + 6)) & 0x1FFFFFu;  // cols p-10..p+10
            unsigned wl = win & 0x7FFu;
            int dl = __clz(wl) - 21;
            unsigned wr = (win >> 10) | 0x800u;
            int dr = __ffs((int)wr) - 1;
            int f = min(min(dl, dr), 10);
            f2p[u] = f * f;
        }
        hout[j] = __floats2half2_rn((float)f2p[0], (float)f2p[1]);
    }
    uint4* dst = (uint4*)(g_f2h + (size_t)row * WW + lane * 16);
    dst[0] = *(uint4*)&hout[0];
    dst[1] = *(uint4*)&hout[4];
}

// ---------------------------------------------------------------------------
// K2: per 32x64 tile (2048 CTAs for latency hiding):
//  1) copy fp16 f^2 halo (52x64) into smem — straight uint4 copy
//  2) fully-unrolled 21-tap half2 min-plus, compile-time (di)^2 weights
//     (exact integers in fp16, <= 200); acc init = 100 (heatmap ~ 0 there)
//  3) branch-free epilogue, 4 rows x 2 cols per thread: p=sigmoid(inp),
//     h=exp(-dmin/8); bg-uniform f=0.15p^2, l=0.15(p(p-h))^2; fg px
//     (dmin==0, h=1 exact) rare per-thread correction
//  4) shuffle reduce; last block folds the final scalar.
// ---------------------------------------------------------------------------
__global__ __launch_bounds__(256) void k2_main(const float* __restrict__ inp,
                                               float* __restrict__ out) {
    const int tid = threadIdx.x;
    const int tx = tid & 31;  // cols 2tx, 2tx+1
    const int ty = tid >> 5;  // rows ty*4 .. ty*4+3
    const int j0 = blockIdx.x * TILE_W;
    const int i0 = blockIdx.y * TILE_H;
    const int b = blockIdx.z;

    __shared__ __align__(16) __half2 sf2[SROWS][TILE_W / 2];  // 6.5 KB
    __shared__ float swF[8];
    __shared__ float swL[8];
    __shared__ int slast;

    // --- 1) halo copy: 52 rows x 8 uint4 = 416 vectors ---
    const uint4 sent = make_uint4(0x56405640u, 0x56405640u, 0x56405640u,
                                  0x56405640u);  // half(100) x8
    for (int e = tid; e < SROWS * 8; e += 256) {
        int rr = e >> 3;
        int c = e & 7;
        int gr = i0 - RAD + rr;
        uint4 v = sent;
        if ((unsigned)gr < HH)
            v = *(const uint4*)(g_f2h + ((size_t)(b * HH + gr)) * WW + j0 + c * 8);
        ((uint4*)&sf2[rr][0])[c] = v;
    }
    __syncthreads();

    // --- 2) dense 21-tap min-plus, compile-time weights ---
    const int r0 = ty * 4;
    __half2 acc[4];
#pragma unroll
    for (int mm = 0; mm < 4; mm++) acc[mm] = __float2half2_rn(100.0f);
#pragma unroll
    for (int t = 0; t < 4 - 1 + 2 * RAD + 1; t++) {  // 24 taps
        __half2 v = sf2[r0 + t][tx];
#pragma unroll
        for (int mm = 0; mm < 4; mm++) {
            const int dk = t - mm;
            if (dk >= 0 && dk <= 2 * RAD) {
                const float wgt = (float)((dk - RAD) * (dk - RAD));
                acc[mm] = __hmin2(acc[mm], __hadd2(v, __float2half2_rn(wgt)));
            }
        }
    }

    // --- 3) epilogue: 4 rows x 2 cols, branch-free ---
    const float* ib = inp + ((size_t)(b * HH + i0 + r0)) * WW + j0 + 2 * tx;
    float fsum = 0.0f, lsum = 0.0f;
    float mn = 100.0f;
#pragma unroll
    for (int mm = 0; mm < 4; mm++) {
        float2 x2 = *(const float2*)(ib + (size_t)mm * WW);
        float2 dd = __half22float2(acc[mm]);
        mn = fminf(mn, fminf(dd.x, dd.y));
        float p0 = __fdividef(1.0f, 1.0f + __expf(-x2.x));
        float h0 = __expf(dd.x * -0.125f);
        fsum = fmaf(p0, p0, fsum);
        float t0 = p0 * (p0 - h0);
        lsum = fmaf(t0, t0, lsum);
        float p1 = __fdividef(1.0f, 1.0f + __expf(-x2.y));
        float h1 = __expf(dd.y * -0.125f);
        fsum = fmaf(p1, p1, fsum);
        float t1 = p1 * (p1 - h1);
        lsum = fmaf(t1, t1, lsum);
    }
    float thF = 0.15f * fsum;
    float thL = 0.15f * lsum;

    if (mn == 0.0f) {  // rare: thread owns >=1 foreground pixel
        for (int mm = 0; mm < 4; mm++) {
            float2 x2 = *(const float2*)(ib + (size_t)mm * WW);
            float2 dd = __half22float2(acc[mm]);
            if (dd.x == 0.0f) {
                float p = __fdividef(1.0f, 1.0f + __expf(-x2.x));
                float qq = 1.0f - p;
                float cf = 0.85f * qq * qq - 0.15f * p * p;
                thF += cf;
                thL += qq * qq * cf;
            }
            if (dd.y == 0.0f) {
                float p = __fdividef(1.0f, 1.0f + __expf(-x2.y));
                float qq = 1.0f - p;
                float cf = 0.85f * qq * qq - 0.15f * p * p;
                thF += cf;
                thL += qq * qq * cf;
            }
        }
    }

    // --- 4) shuffle reduction (fixed order -> deterministic) ---
#pragma unroll
    for (int off = 16; off > 0; off >>= 1) {
        thF += __shfl_xor_sync(0xffffffffu, thF, off);
        thL += __shfl_xor_sync(0xffffffffu, thL, off);
    }
    if (tx == 0) {
        swF[ty] = thF;
        swL[ty] = thL;
    }
    __syncthreads();

    const int bid = blockIdx.x + GX * (blockIdx.y + GYT * blockIdx.z);
    if (tid == 0) {
        float F = 0.0f, Lv = 0.0f;
#pragma unroll
        for (int w = 0; w < 8; w++) {
            F += swF[w];
            Lv += swL[w];
        }
        g_pf[bid] = F;
        g_pl[bid] = Lv;
        __threadfence();
        unsigned old = atomicAdd(&g_done, 1u);
        slast = (old == NB - 1) ? 1 : 0;
    }
    __syncthreads();

    // --- last block: fold final scalar (reuses sf2 as double scratch) ---
    if (slast) {
        __threadfence();
        double* sFd = (double*)&sf2[0][0];
        double* sLd = sFd + 256;
        double f = 0.0, l = 0.0;
        for (int i = tid; i < NB; i += 256) {
            f += (double)g_pf[i];
            l += (double)g_pl[i];
        }
        sFd[tid] = f;
        sLd[tid] = l;
        __syncthreads();
#pragma unroll
        for (int s = 128; s > 0; s >>= 1) {
            if (tid < s) {
                sFd[tid] += sFd[tid + s];
                sLd[tid] += sLd[tid + s];
            }
            __syncthreads();
        }
        if (tid == 0) {
            double n = (double)NTOT;
            double denom = sFd[0] / n + 0.01;
            out[0] = (float)(2.0 * (sLd[0] / n) / denom);
            g_done = 0;  // reset for next graph replay
        }
    }
}

extern "C" void kernel_launch(void* const* d_in, const int* in_sizes, int n_in,
                              void* d_out, int out_size) {
    const float* inp = (const float*)d_in[0];
    const float* tgt = (const float*)d_in[1];
    float* out = (float*)d_out;

    k1_f2<<<(BB * HH * 32) / 256, 256>>>(tgt);
    dim3 g2(GX, GYT, BB);
    k2_main<<<g2, 256>>>(inp, out);
}

// round 11
// speedup vs baseline: 1.0156x; 1.0156x over previous
#include <cuda_runtime.h>
#include <math.h>

#define BB 16
#define HH 512
#define WW 512
#define NTOT (BB * HH * WW)

#define RAD 10
#define TILE_H 32
#define TILE_W 64
#define SROWS (TILE_H + 2 * RAD)  // 52
#define GX (WW / TILE_W)          // 8
#define GYT (HH / TILE_H)         // 16
#define NB (GX * GYT * BB)        // 2048

// Scratch (no allocation allowed in kernel_launch)
__device__ unsigned g_mask[BB * HH * 16];  // fg bitmask, 16 u32 words per row
__device__ float g_pl[NB];
__device__ float g_pf[NB];
__device__ unsigned g_done = 0;  // last-block counter (self-resetting)

// ---------------------------------------------------------------------------
// K1: build fg bitmask. Pure streaming: each thread loads 4 independent
// float4s (16 cols), builds 16 bits locally, stores one u16. MLP=4/thread.
// ---------------------------------------------------------------------------
__global__ __launch_bounds__(256) void k1_mask(const float* __restrict__ tgt) {
    const int gid = blockIdx.x * 256 + threadIdx.x;
    const int row = gid >> 5;
    const int c16 = gid & 31;
    const float4* p = (const float4*)(tgt + (size_t)row * WW + c16 * 16);
    float4 v0 = p[0], v1 = p[1], v2 = p[2], v3 = p[3];
    unsigned m = 0;
    m |= (v0.x > 0.5f) ? 1u << 0 : 0u;
    m |= (v0.y > 0.5f) ? 1u << 1 : 0u;
    m |= (v0.z > 0.5f) ? 1u << 2 : 0u;
    m |= (v0.w > 0.5f) ? 1u << 3 : 0u;
    m |= (v1.x > 0.5f) ? 1u << 4 : 0u;
    m |= (v1.y > 0.5f) ? 1u << 5 : 0u;
    m |= (v1.z > 0.5f) ? 1u << 6 : 0u;
    m |= (v1.w > 0.5f) ? 1u << 7 : 0u;
    m |= (v2.x > 0.5f) ? 1u << 8 : 0u;
    m |= (v2.y > 0.5f) ? 1u << 9 : 0u;
    m |= (v2.z > 0.5f) ? 1u << 10 : 0u;
    m |= (v2.w > 0.5f) ? 1u << 11 : 0u;
    m |= (v3.x > 0.5f) ? 1u << 12 : 0u;
    m |= (v3.y > 0.5f) ? 1u << 13 : 0u;
    m |= (v3.z > 0.5f) ? 1u << 14 : 0u;
    m |= (v3.w > 0.5f) ? 1u << 15 : 0u;
    ((unsigned short*)g_mask)[(size_t)row * 32 + c16] = (unsigned short)m;
}

// ---------------------------------------------------------------------------
// K2: per 32x64 tile, sparse vertical pass.
//  1) stage 52 rows x 4 mask words (cols j0-32..j0+95) into smem; build a
//     52-bit row-activity mask (row active iff any fg bit in cols
//     [j0-10, j0+73]) via idempotent atomicOr.
//  2) each warp (4 output rows x 64 cols): tap loop over ACTIVE halo rows
//     only (warp-uniform ffs loop, ~2 iterations avg). Per tap: f^2 for the
//     lane's 2 cols from mask bits (funnelshift+clz/ffs, clamp 10), then
//     min-plus with runtime weight w = min(dm^2, 100) — exact small ints in
//     fp32; the clamp uniformly neutralizes out-of-window taps (dm^2 > 100)
//     and ties with the sentinel 100.
//  3) branch-free epilogue: p=sigmoid(inp), h=exp(-dmin/8); bg-uniform
//     f=0.15p^2, l=0.15(p(p-h))^2; fg px (dmin==0 exact, h=1) rare correction.
//  4) shuffle reduce; last block folds the final scalar.
// dmin=100 where no fg within dist 10 -> h=exp(-12.5)=3.7e-6 ~ true heatmap
// bound exp(-100/8) -> loss-equivalent well within 1e-3.
// ---------------------------------------------------------------------------
__global__ __launch_bounds__(256) void k2_main(const float* __restrict__ inp,
                                               float* __restrict__ out) {
    const int tid = threadIdx.x;
    const int tx = tid & 31;  // cols 2tx, 2tx+1
    const int ty = tid >> 5;  // rows ty*4 .. ty*4+3
    const int j0 = blockIdx.x * TILE_W;
    const int i0 = blockIdx.y * TILE_H;
    const int b = blockIdx.z;

    __shared__ __align__(16) unsigned smask[SROWS][4];  // 832 B
    __shared__ unsigned srm[2];                         // 52-bit row activity
    __shared__ float swF[8];
    __shared__ float swL[8];
    __shared__ int slast;
    __shared__ double sred[512];  // finalize scratch (4 KB)

    if (tid < 2) srm[tid] = 0;
    __syncthreads();

    // --- 1) stage mask words + row-activity flags ---
    const int q = j0 >> 5;
    const unsigned* mb = g_mask + (size_t)b * HH * 16;
    for (int e = tid; e < SROWS * 4; e += 256) {
        int rr = e >> 2;
        int wi = e & 3;
        int gr = i0 - RAD + rr;
        int gw = q - 1 + wi;
        unsigned v = 0;
        if ((unsigned)gr < HH && (unsigned)gw < 16u) v = mb[gr * 16 + gw];
        smask[rr][wi] = v;
        // activity window: cols [j0-10, j0+73]
        unsigned wm = (wi == 0) ? 0xFFC00000u : ((wi == 3) ? 0x000003FFu : 0xFFFFFFFFu);
        if (v & wm) atomicOr(&srm[rr >> 5], 1u << (rr & 31));
    }
    __syncthreads();

    // --- 2) sparse tap loop (warp-uniform) ---
    const int r0 = ty * 4;
    unsigned long long rmall =
        (unsigned long long)srm[0] | ((unsigned long long)srm[1] << 32);
    unsigned rm = (unsigned)((rmall >> r0) & 0xFFFFFFu);  // taps 0..23

    float acc0[4], acc1[4];
#pragma unroll
    for (int mm = 0; mm < 4; mm++) {
        acc0[mm] = 100.0f;
        acc1[mm] = 100.0f;
    }

    while (rm) {
        int t = __ffs(rm) - 1;
        rm &= rm - 1;
        // f^2 for cols 2tx, 2tx+1 at halo row r0+t, from mask bits
        uint4 mw = *(const uint4*)&smask[r0 + t][0];
        float f2v[2];
#pragma unroll
        for (int u = 0; u < 2; u++) {
            int c = 2 * tx + u;       // tile col; global bit = c + 32
            int bs = c + 22;          // window start bit (col c-10)
            int k = bs >> 5;          // 0..2
            int sh = bs & 31;
            unsigned lo = (k == 0) ? mw.x : ((k == 1) ? mw.y : mw.z);
            unsigned hi = (k == 0) ? mw.y : ((k == 1) ? mw.z : mw.w);
            unsigned win = __funnelshift_r(lo, hi, sh) & 0x1FFFFFu;  // c-10..c+10
            unsigned wl = win & 0x7FFu;          // c-10..c (bit10 = center)
            int dl = __clz(wl) - 21;             // 0..11
            unsigned wr = (win >> 10) | 0x800u;  // c..c+10 + sentinel
            int dr = __ffs((int)wr) - 1;         // 0..11
            int f = min(min(dl, dr), 10);
            f2v[u] = (float)(f * f);
        }
        int tm10 = t - 10;
#pragma unroll
        for (int mm = 0; mm < 4; mm++) {
            int dm = tm10 - mm;
            float w = (float)min(dm * dm, 100);  // clamps invalid taps too
            acc0[mm] = fminf(acc0[mm], f2v[0] + w);
            acc1[mm] = fminf(acc1[mm], f2v[1] + w);
        }
    }

    // --- 3) epilogue: 4 rows x 2 cols, branch-free ---
    const float* ib = inp + ((size_t)(b * HH + i0 + r0)) * WW + j0 + 2 * tx;
    float fsum = 0.0f, lsum = 0.0f;
    float mn = 100.0f;
#pragma unroll
    for (int mm = 0; mm < 4; mm++) {
        float2 x2 = *(const float2*)(ib + (size_t)mm * WW);
        mn = fminf(mn, fminf(acc0[mm], acc1[mm]));
        float p0 = __fdividef(1.0f, 1.0f + __expf(-x2.x));
        float h0 = __expf(acc0[mm] * -0.125f);
        fsum = fmaf(p0, p0, fsum);
        float t0 = p0 * (p0 - h0);
        lsum = fmaf(t0, t0, lsum);
        float p1 = __fdividef(1.0f, 1.0f + __expf(-x2.y));
        float h1 = __expf(acc1[mm] * -0.125f);
        fsum = fmaf(p1, p1, fsum);
        float t1 = p1 * (p1 - h1);
        lsum = fmaf(t1, t1, lsum);
    }
    float thF = 0.15f * fsum;
    float thL = 0.15f * lsum;

    if (mn == 0.0f) {  // rare: thread owns >=1 foreground pixel
        for (int mm = 0; mm < 4; mm++) {
            float2 x2 = *(const float2*)(ib + (size_t)mm * WW);
            if (acc0[mm] == 0.0f) {
                float p = __fdividef(1.0f, 1.0f + __expf(-x2.x));
                float qq = 1.0f - p;
                float cf = 0.85f * qq * qq - 0.15f * p * p;
                thF += cf;
                thL += qq * qq * cf;
            }
            if (acc1[mm] == 0.0f) {
                float p = __fdividef(1.0f, 1.0f + __expf(-x2.y));
                float qq = 1.0f - p;
                float cf = 0.85f * qq * qq - 0.15f * p * p;
                thF += cf;
                thL += qq * qq * cf;
            }
        }
    }

    // --- 4) shuffle reduction (fixed order -> deterministic) ---
#pragma unroll
    for (int off = 16; off > 0; off >>= 1) {
        thF += __shfl_xor_sync(0xffffffffu, thF, off);
        thL += __shfl_xor_sync(0xffffffffu, thL, off);
    }
    if (tx == 0) {
        swF[ty] = thF;
        swL[ty] = thL;
    }
    __syncthreads();

    const int bid = blockIdx.x + GX * (blockIdx.y + GYT * blockIdx.z);
    if (tid == 0) {
        float F = 0.0f, Lv = 0.0f;
#pragma unroll
        for (int w = 0; w < 8; w++) {
            F += swF[w];
            Lv += swL[w];
        }
        g_pf[bid] = F;
        g_pl[bid] = Lv;
        __threadfence();
        unsigned old = atomicAdd(&g_done, 1u);
        slast = (old == NB - 1) ? 1 : 0;
    }
    __syncthreads();

    // --- last block: fold final scalar ---
    if (slast) {
        __threadfence();
        double* sFd = sred;
        double* sLd = sred + 256;
        double f = 0.0, l = 0.0;
        for (int i = tid; i < NB; i += 256) {
            f += (double)g_pf[i];
            l += (double)g_pl[i];
        }
        sFd[tid] = f;
        sLd[tid] = l;
        __syncthreads();
#pragma unroll
        for (int s = 128; s > 0; s >>= 1) {
            if (tid < s) {
                sFd[tid] += sFd[tid + s];
                sLd[tid] += sLd[tid + s];
            }
            __syncthreads();
        }
        if (tid == 0) {
            double n = (double)NTOT;
            double denom = sFd[0] / n + 0.01;
            out[0] = (float)(2.0 * (sLd[0] / n) / denom);
            g_done = 0;  // reset for next graph replay
        }
    }
}

extern "C" void kernel_launch(void* const* d_in, const int* in_sizes, int n_in,
                              void* d_out, int out_size) {
    const float* inp = (const float*)d_in[0];
    const float* tgt = (const float*)d_in[1];
    float* out = (float*)d_out;

    k1_mask<<<(BB * HH * 32) / 256, 256>>>(tgt);
    dim3 g2(GX, GYT, BB);
    k2_main<<<g2, 256>>>(inp, out);
}